// round 3
// baseline (speedup 1.0000x reference)
#include <cuda_runtime.h>
#include <cstdint>

// PositionEncoding: out[b,s,d] = x[b,s,d] + pe[s,d]
//   pe[s,d] = sin(s / 10000^(d/D)) if d even else cos(s / 10000^(d/D))
// Shapes: B=8, S=4096, D=1024 (fp32).
//
// R3: two-group software pipeline (4+4 batches) to cap registers at ~40 and
// recover occupancy (6 CTAs/SM = 48 warps) while keeping burst-structured
// loads/stores. Streaming cache hints (ldcs/stcs): all data is touch-once.

static constexpr int B = 8;
static constexpr int S = 4096;
static constexpr int D = 1024;
static constexpr int D4 = D / 4;                  // 256 float4 per row
static constexpr int SD4 = S * D4;                // 1,048,576
static constexpr long long BSTR = (long long)S * D4;   // batch stride in float4

// log2(10000) / D  (D = 1024)
static constexpr float LOG2_10000_OVER_D = 13.287712379549449f / 1024.0f;

__global__ __launch_bounds__(256, 6)
void pe_add_kernel(const float4* __restrict__ x, float4* __restrict__ out) {
    int idx = blockIdx.x * blockDim.x + threadIdx.x;   // grid exactly covers SD4

    const float4* __restrict__ xp = x + idx;
    float4* __restrict__ op = out + idx;

    // ---- group 0: batches 0..3, front-batched loads ----
    float4 v0 = __ldcs(xp + 0 * BSTR);
    float4 v1 = __ldcs(xp + 1 * BSTR);
    float4 v2 = __ldcs(xp + 2 * BSTR);
    float4 v3 = __ldcs(xp + 3 * BSTR);

    // ---- trig while group-0 loads are in flight ----
    int s  = idx >> 8;          // idx / D4
    int d4 = idx & (D4 - 1);    // idx % D4
    int d  = d4 << 2;
    float fs = (float)s;

    float a0 = fs * exp2f(-(float)(d + 0) * LOG2_10000_OVER_D);
    float a1 = fs * exp2f(-(float)(d + 1) * LOG2_10000_OVER_D);
    float a2 = fs * exp2f(-(float)(d + 2) * LOG2_10000_OVER_D);
    float a3 = fs * exp2f(-(float)(d + 3) * LOG2_10000_OVER_D);

    float pex = sinf(a0);   // even dim -> sin
    float pey = cosf(a1);   // odd dim  -> cos
    float pez = sinf(a2);
    float pew = cosf(a3);

    // ---- group 1 loads: batches 4..7 (overlap with group-0 stores) ----
    float4 w0 = __ldcs(xp + 4 * BSTR);
    float4 w1 = __ldcs(xp + 5 * BSTR);
    float4 w2 = __ldcs(xp + 6 * BSTR);
    float4 w3 = __ldcs(xp + 7 * BSTR);

    // ---- store group 0 ----
    v0.x += pex; v0.y += pey; v0.z += pez; v0.w += pew;
    __stcs(op + 0 * BSTR, v0);
    v1.x += pex; v1.y += pey; v1.z += pez; v1.w += pew;
    __stcs(op + 1 * BSTR, v1);
    v2.x += pex; v2.y += pey; v2.z += pez; v2.w += pew;
    __stcs(op + 2 * BSTR, v2);
    v3.x += pex; v3.y += pey; v3.z += pez; v3.w += pew;
    __stcs(op + 3 * BSTR, v3);

    // ---- store group 1 ----
    w0.x += pex; w0.y += pey; w0.z += pez; w0.w += pew;
    __stcs(op + 4 * BSTR, w0);
    w1.x += pex; w1.y += pey; w1.z += pez; w1.w += pew;
    __stcs(op + 5 * BSTR, w1);
    w2.x += pex; w2.y += pey; w2.z += pez; w2.w += pew;
    __stcs(op + 6 * BSTR, w2);
    w3.x += pex; w3.y += pey; w3.z += pez; w3.w += pew;
    __stcs(op + 7 * BSTR, w3);
}

extern "C" void kernel_launch(void* const* d_in, const int* in_sizes, int n_in,
                              void* d_out, int out_size) {
    const float4* x = (const float4*)d_in[0];
    float4* out = (float4*)d_out;

    int threads = 256;
    int blocks = SD4 / threads;   // 4096, exact
    pe_add_kernel<<<blocks, threads>>>(x, out);
}

// round 4
// speedup vs baseline: 1.0137x; 1.0137x over previous
#include <cuda_runtime.h>
#include <cstdint>

// PositionEncoding: out[b,s,d] = x[b,s,d] + pe[s,d]
//   pe[s,d] = sin(s / 10000^(d/D)) if d even else cos(s / 10000^(d/D))
// Shapes: B=8, S=4096, D=1024 (fp32).
//
// R4: cp.async (LDGSTS) into smem for the 8 batch loads — load data never
// touches the register file, so MLP=8 per warp coexists with high occupancy
// (smem-limited: 32KB/CTA -> 7 CTAs/SM = 56 warps). Trig overlaps the async
// wait. Target: maximize in-flight bytes/SM to fill DRAM idle cycles.

static constexpr int B = 8;
static constexpr int S = 4096;
static constexpr int D = 1024;
static constexpr int D4 = D / 4;                  // 256 float4 per row
static constexpr int SD4 = S * D4;                // 1,048,576
static constexpr long long BSTR = (long long)S * D4;   // batch stride (float4)

// log2(10000) / D  (D = 1024)
static constexpr float LOG2_10000_OVER_D = 13.287712379549449f / 1024.0f;

__global__ __launch_bounds__(256)
void pe_add_kernel(const float4* __restrict__ x, float4* __restrict__ out) {
    __shared__ float4 buf[B * 256];                // 32 KB

    int t = threadIdx.x;
    int idx = blockIdx.x * 256 + t;                // grid exactly covers SD4

    // ---- issue 8 async 16B copies (batch-strided), data lands in smem ----
    unsigned sdst = (unsigned)__cvta_generic_to_shared(&buf[t]);
    const float4* __restrict__ gp = x + idx;
#pragma unroll
    for (int b = 0; b < B; b++) {
        asm volatile("cp.async.cg.shared.global [%0], [%1], 16;\n"
                     :: "r"(sdst + b * (256 * 16)), "l"(gp + b * BSTR)
                     : "memory");
    }
    asm volatile("cp.async.commit_group;\n" ::: "memory");

    // ---- trig while the copies are in flight ----
    int s  = idx >> 8;          // idx / D4
    int d4 = idx & (D4 - 1);    // idx % D4
    int d  = d4 << 2;
    float fs = (float)s;

    float a0 = fs * exp2f(-(float)(d + 0) * LOG2_10000_OVER_D);
    float a1 = fs * exp2f(-(float)(d + 1) * LOG2_10000_OVER_D);
    float a2 = fs * exp2f(-(float)(d + 2) * LOG2_10000_OVER_D);
    float a3 = fs * exp2f(-(float)(d + 3) * LOG2_10000_OVER_D);

    float pex = sinf(a0);   // even dim -> sin
    float pey = cosf(a1);   // odd dim  -> cos
    float pez = sinf(a2);
    float pew = cosf(a3);

    // ---- wait for all copies issued by this thread ----
    asm volatile("cp.async.wait_group 0;\n" ::: "memory");

    // ---- read back from smem, add, store (each thread reads its own data) ----
    float4* __restrict__ op = out + idx;
#pragma unroll
    for (int b = 0; b < B; b++) {
        float4 v = buf[b * 256 + t];
        v.x += pex;
        v.y += pey;
        v.z += pez;
        v.w += pew;
        __stcg(op + b * BSTR, v);
    }
}

extern "C" void kernel_launch(void* const* d_in, const int* in_sizes, int n_in,
                              void* d_out, int out_size) {
    const float4* x = (const float4*)d_in[0];
    float4* out = (float4*)d_out;

    int threads = 256;
    int blocks = SD4 / threads;   // 4096, exact
    pe_add_kernel<<<blocks, threads>>>(x, out);
}